// round 4
// baseline (speedup 1.0000x reference)
#include <cuda_runtime.h>
#include <math.h>

// ---------------------------------------------------------------------------
// RandomProjection: out[b,o] = mean_s( cos(x[b,s,:], p[o,:]) )
//   m[b,:] = mean_s( x[b,s,:] / max(||x[b,s]||, eps) )   (kernel 1 + in-kernel combine)
//   out[b,o] = (m[b,:] . p[o,:]) / max(||p[o]||, eps)    (kernel 2)
// ---------------------------------------------------------------------------

#define B_   32
#define S_   512
#define D_   768
#define O_   2048
#define EPS_ 1e-8f
#define PQ_  4

__device__ float g_part[PQ_ * B_ * D_];   // race-free partials
__device__ float g_m[B_ * D_];            // combined mean (written by ticket winner)
__device__ int   g_ticket[B_];            // zero-init; reset to 0 by winner

// ---- packed f32x2 helpers --------------------------------------------------
__device__ __forceinline__ void fma2(unsigned long long& d,
                                     unsigned long long a,
                                     unsigned long long b) {
    asm("fma.rn.f32x2 %0, %1, %2, %3;" : "=l"(d) : "l"(a), "l"(b), "l"(d));
}
__device__ __forceinline__ float unpack_sum(unsigned long long v) {
    float lo, hi;
    asm("mov.b64 {%0, %1}, %2;" : "=f"(lo), "=f"(hi) : "l"(v));
    return lo + hi;
}

// ---------------------------------------------------------------------------
// Kernel 1: per-row normalize + partial mean; 4th block per b combines.
// Grid: 128 blocks = (b, quarter q). Block: 512 threads = 16 warps.
// ---------------------------------------------------------------------------
__global__ void __launch_bounds__(512, 1)
reduce_x_kernel(const float* __restrict__ x) {
    __shared__ float4 sm[16 * 192];   // 48 KB
    __shared__ int is_last;

    const int q    = blockIdx.x & 3;
    const int b    = blockIdx.x >> 2;
    const int warp = threadIdx.x >> 5;
    const int lane = threadIdx.x & 31;

    const float4* base = reinterpret_cast<const float4*>(
        x + ((size_t)b * S_ + (size_t)q * 128 + (size_t)warp * 8) * D_);

    const float inv_S = 1.0f / (float)S_;

    float4 acc[6];
    #pragma unroll
    for (int c = 0; c < 6; c++) acc[c] = make_float4(0.f, 0.f, 0.f, 0.f);

    float4 v[6];
    #pragma unroll
    for (int c = 0; c < 6; c++) v[c] = base[lane + 32 * c];

    #pragma unroll
    for (int r = 0; r < 8; r++) {
        float4 vn[6];
        if (r < 7) {
            #pragma unroll
            for (int c = 0; c < 6; c++)
                vn[c] = base[(r + 1) * 192 + lane + 32 * c];
        }

        float ss = 0.f;
        #pragma unroll
        for (int c = 0; c < 6; c++)
            ss += v[c].x * v[c].x + v[c].y * v[c].y
                + v[c].z * v[c].z + v[c].w * v[c].w;
        #pragma unroll
        for (int off = 16; off > 0; off >>= 1)
            ss += __shfl_xor_sync(0xFFFFFFFFu, ss, off);

        const float scale = inv_S / fmaxf(sqrtf(ss), EPS_);

        #pragma unroll
        for (int c = 0; c < 6; c++) {
            acc[c].x += v[c].x * scale;
            acc[c].y += v[c].y * scale;
            acc[c].z += v[c].z * scale;
            acc[c].w += v[c].w * scale;
        }

        if (r < 7) {
            #pragma unroll
            for (int c = 0; c < 6; c++) v[c] = vn[c];
        }
    }

    #pragma unroll
    for (int c = 0; c < 6; c++)
        sm[warp * 192 + lane + 32 * c] = acc[c];
    __syncthreads();

    if (threadIdx.x < 192) {
        float4 s = sm[threadIdx.x];
        #pragma unroll
        for (int w = 1; w < 16; w++) {
            const float4 t = sm[w * 192 + threadIdx.x];
            s.x += t.x; s.y += t.y; s.z += t.z; s.w += t.w;
        }
        reinterpret_cast<float4*>(g_part)[((q * B_ + b) * 192) + threadIdx.x] = s;
    }

    // ticket: last of the 4 blocks for this b combines partials -> g_m[b]
    __threadfence();
    if (threadIdx.x == 0)
        is_last = (atomicAdd(&g_ticket[b], 1) == 3) ? 1 : 0;
    __syncthreads();

    if (is_last) {
        __threadfence();   // acquire: see other blocks' partial stores
        if (threadIdx.x < 192) {
            const float4* gp = reinterpret_cast<const float4*>(g_part);
            float4 a  = gp[(0 * B_ + b) * 192 + threadIdx.x];
            const float4 b4 = gp[(1 * B_ + b) * 192 + threadIdx.x];
            const float4 c4 = gp[(2 * B_ + b) * 192 + threadIdx.x];
            const float4 d4 = gp[(3 * B_ + b) * 192 + threadIdx.x];
            a.x += b4.x + c4.x + d4.x;
            a.y += b4.y + c4.y + d4.y;
            a.z += b4.z + c4.z + d4.z;
            a.w += b4.w + c4.w + d4.w;
            reinterpret_cast<float4*>(g_m)[b * 192 + threadIdx.x] = a;
        }
        if (threadIdx.x == 0) g_ticket[b] = 0;   // reset for next replay
    }
}

// ---------------------------------------------------------------------------
// Kernel 2: out[b,o] = (m[b,:] . p[o,:]) / max(||p[o]||, eps)
// Grid: 512 blocks x 128 threads. Block: 8 o-rows x 16 b. Warp: 8 o x 4 b.
// 32 ull accumulators (f32x2); butterfly transpose-reduce; lane l ends with
// output (b0 + (l>>3), o0 + (l&7)).
// ---------------------------------------------------------------------------
__global__ void __launch_bounds__(128, 1)
gemm_kernel(const float* __restrict__ p, float* __restrict__ out) {
    const int warp = threadIdx.x >> 5;
    const int lane = threadIdx.x & 31;
    const int ot   = blockIdx.x >> 1;          // o-tile (256)
    const int bh   = blockIdx.x & 1;           // b half
    const int o0   = ot * 8;
    const int b0   = bh * 16 + warp * 4;

    unsigned long long acc[32];   // idx = bb*8 + oo
    unsigned long long ss[8];
    #pragma unroll
    for (int i = 0; i < 32; i++) acc[i] = 0ull;
    #pragma unroll
    for (int i = 0; i < 8; i++)  ss[i]  = 0ull;

    #pragma unroll
    for (int c = 0; c < 6; c++) {
        ulonglong2 pv[8];
        #pragma unroll
        for (int oo = 0; oo < 8; oo++)
            pv[oo] = reinterpret_cast<const ulonglong2*>(
                         p + (size_t)(o0 + oo) * D_)[lane + 32 * c];
        ulonglong2 mv[4];
        #pragma unroll
        for (int bb = 0; bb < 4; bb++)
            mv[bb] = reinterpret_cast<const ulonglong2*>(
                         g_m + (size_t)(b0 + bb) * D_)[lane + 32 * c];

        #pragma unroll
        for (int oo = 0; oo < 8; oo++) {
            fma2(ss[oo], pv[oo].x, pv[oo].x);
            fma2(ss[oo], pv[oo].y, pv[oo].y);
        }
        #pragma unroll
        for (int bb = 0; bb < 4; bb++)
            #pragma unroll
            for (int oo = 0; oo < 8; oo++) {
                fma2(acc[bb * 8 + oo], mv[bb].x, pv[oo].x);
                fma2(acc[bb * 8 + oo], mv[bb].y, pv[oo].y);
            }
    }

    // ---- p-norms: 8-slot butterfly within 8-lane groups, then fold groups
    float s8[8];
    #pragma unroll
    for (int i = 0; i < 8; i++) s8[i] = unpack_sum(ss[i]);
    #pragma unroll
    for (int k = 1; k < 8; k <<= 1) {
        const bool hi = (lane & k) != 0;
        #pragma unroll
        for (int i = 0; i < 8; i += 2 * k) {
            #pragma unroll
            for (int j = 0; j < k; j++) {
                const int lo_i = i + j, hi_i = i + j + k;
                const float send = hi ? s8[lo_i] : s8[hi_i];
                const float recv = __shfl_xor_sync(0xFFFFFFFFu, send, k);
                if (hi) s8[hi_i] += recv; else s8[lo_i] += recv;
            }
        }
    }
    float nrm = s8[lane & 7];
    nrm += __shfl_xor_sync(0xFFFFFFFFu, nrm, 8);
    nrm += __shfl_xor_sync(0xFFFFFFFFu, nrm, 16);
    const float rn = 1.0f / fmaxf(sqrtf(nrm), EPS_);  // norm of o-row (lane&7)

    // ---- 32-slot butterfly transpose-reduce: lane l ends with slot l
    float r[32];
    #pragma unroll
    for (int i = 0; i < 32; i++) r[i] = unpack_sum(acc[i]);
    #pragma unroll
    for (int k = 1; k < 32; k <<= 1) {
        const bool hi = (lane & k) != 0;
        #pragma unroll
        for (int i = 0; i < 32; i += 2 * k) {
            #pragma unroll
            for (int j = 0; j < k; j++) {
                const int lo_i = i + j, hi_i = i + j + k;
                const float send = hi ? r[lo_i] : r[hi_i];
                const float recv = __shfl_xor_sync(0xFFFFFFFFu, send, k);
                if (hi) r[hi_i] += recv; else r[lo_i] += recv;
            }
        }
    }

    // slot l = (bb = l>>3, oo = l&7); rn on this lane is for o-row (lane&7) ✓
    out[(size_t)(b0 + (lane >> 3)) * O_ + o0 + (lane & 7)] = r[lane] * rn;
}

// ---------------------------------------------------------------------------
extern "C" void kernel_launch(void* const* d_in, const int* in_sizes, int n_in,
                              void* d_out, int out_size) {
    const float* x = (const float*)d_in[0];   // [32, 512, 768]
    const float* p = (const float*)d_in[1];   // [2048, 768]
    float*     out = (float*)d_out;           // [32, 2048]

    (void)in_sizes; (void)n_in; (void)out_size;

    reduce_x_kernel<<<B_ * PQ_, 512>>>(x);
    gemm_kernel<<<512, 128>>>(p, out);
}